// round 4
// baseline (speedup 1.0000x reference)
#include <cuda_runtime.h>

#define NB     8
#define NATOM  512
#define NFEAT  42
#define NNEIGH 100
#define NPT    256
#define NH1    64
#define NH2    32

// scratch for dE (input gradient), computed by ei_kernel, consumed by force_kernel
__device__ float g_dE[NB * NATOM * NFEAT];

// ---------------------------------------------------------------------------
// Kernel 1: per-atom MLP forward + backward.
// Grid: (NB*NATOM)/16 blocks, 128 threads = 2 groups of 64, 8 atoms/group.
// Weights for the block's type cached in SMEM once (all 16 atoms same type:
// 16 | 256 and chunks never cross the type boundary).
// Writes Ei to out[8 + gidx] and dE to g_dE.
// ---------------------------------------------------------------------------
__global__ __launch_bounds__(128) void ei_kernel(
    const float* __restrict__ image,
    const float* __restrict__ W0, const float* __restrict__ b0,
    const float* __restrict__ W1, const float* __restrict__ b1,
    const float* __restrict__ W2, const float* __restrict__ b2,
    float* __restrict__ out)
{
    __shared__ float sW0[NH1 * NFEAT];   // 64 x 42
    __shared__ float sW1[NH2 * NH1];     // 32 x 64
    __shared__ float sW2[NH2];
    __shared__ float sb0[NH1];
    __shared__ float sb1[NH2];
    __shared__ float sb2v;
    __shared__ float sx [2][NFEAT];
    __shared__ float sh1[2][NH1];
    __shared__ float sh2[2][NH2];
    __shared__ float sg2[2][NH2];
    __shared__ float sg1[2][NH1];

    const int tid = threadIdx.x;
    const int grp = tid >> 6;      // 0 or 1
    const int gt  = tid & 63;      // lane within group

    const int base = blockIdx.x * 16;        // global atom index b*NATOM + a
    const int b    = base / NATOM;
    const int a0   = base % NATOM;
    const int t    = a0 / NPT;               // atom type (0 or 1)

    for (int i = tid; i < NH1 * NFEAT; i += 128) sW0[i] = W0[t * NH1 * NFEAT + i];
    for (int i = tid; i < NH2 * NH1;   i += 128) sW1[i] = W1[t * NH2 * NH1 + i];
    if (tid < NH2) sW2[tid] = W2[t * NH2 + tid];
    if (tid < NH1) sb0[tid] = b0[t * NH1 + tid];
    if (tid < NH2) sb1[tid] = b1[t * NH2 + tid];
    if (tid == 0)  sb2v = b2[t];
    __syncthreads();

    for (int it = 0; it < 8; it++) {
        const int a    = a0 + grp * 8 + it;
        const long gidx = (long)b * NATOM + a;

        // A: load input features
        if (gt < NFEAT) sx[grp][gt] = image[gidx * NFEAT + gt];
        __syncthreads();

        // B: h1 = tanh(W0 x + b0)   (one neuron per thread)
        {
            float s = sb0[gt];
            #pragma unroll
            for (int f = 0; f < NFEAT; f++) s += sx[grp][f] * sW0[gt * NFEAT + f];
            sh1[grp][gt] = tanhf(s);
        }
        __syncthreads();

        // C: h2 = tanh(W1 h1 + b1); g2 = W2 .* (1 - h2^2)
        if (gt < NH2) {
            float s = sb1[gt];
            #pragma unroll
            for (int i = 0; i < NH1; i++) s += sh1[grp][i] * sW1[gt * NH1 + i];
            float h = tanhf(s);
            sh2[grp][gt] = h;
            sg2[grp][gt] = sW2[gt] * (1.0f - h * h);
        }
        __syncthreads();

        // D: Ei = W2 . h2 + b2   (warp reduce; gt<32 is a full warp)
        if (gt < 32) {
            float v = sh2[grp][gt] * sW2[gt];
            #pragma unroll
            for (int o = 16; o > 0; o >>= 1) v += __shfl_down_sync(0xffffffffu, v, o);
            if (gt == 0) out[8 + gidx] = v + sb2v;
        }

        // E: g1 = (W1^T g2) .* (1 - h1^2)
        {
            float s = 0.0f;
            #pragma unroll
            for (int j = 0; j < NH2; j++) s += sg2[grp][j] * sW1[j * NH1 + gt];
            float h = sh1[grp][gt];
            sg1[grp][gt] = s * (1.0f - h * h);
        }
        __syncthreads();

        // F: dx = W0^T g1
        if (gt < NFEAT) {
            float s = 0.0f;
            #pragma unroll
            for (int i = 0; i < NH1; i++) s += sg1[grp][i] * sW0[i * NFEAT + gt];
            g_dE[gidx * NFEAT + gt] = s;
        }
        __syncthreads();
    }
}

// ---------------------------------------------------------------------------
// Kernel 2: Etot[b] = sum_a Ei[b][a]   (deterministic reduction, 8 blocks)
// ---------------------------------------------------------------------------
__global__ __launch_bounds__(256) void etot_kernel(float* __restrict__ out)
{
    __shared__ float red[8];
    const int tid = threadIdx.x;
    const float* Ei = out + 8 + (long)blockIdx.x * NATOM;
    float v = Ei[tid] + Ei[tid + 256];
    #pragma unroll
    for (int o = 16; o > 0; o >>= 1) v += __shfl_down_sync(0xffffffffu, v, o);
    if ((tid & 31) == 0) red[tid >> 5] = v;
    __syncthreads();
    if (tid == 0) {
        float s = 0.0f;
        #pragma unroll
        for (int w = 0; w < 8; w++) s += red[w];
        out[blockIdx.x] = s;
    }
}

// ---------------------------------------------------------------------------
// Kernel 3: Force[b,a,k] = sum_{n,f} dE_padded[b, neighbor[b,a,n], f]
//                                    * dfeat[b,a,n,f,k]
// One block per atom (4096 blocks, 256 threads). Gathered dE tile staged in
// SMEM (4200 floats), then dfeat streamed with LDG.128: 3 float4 = 4 (n,f)
// pairs, k-pattern statically unrolled.
// ---------------------------------------------------------------------------
__global__ __launch_bounds__(256) void force_kernel(
    const float* __restrict__ dfeat,
    const int* __restrict__ neighbor,
    float* __restrict__ out)
{
    __shared__ __align__(16) float sg[NNEIGH * NFEAT];  // 4200 floats
    __shared__ int sn[NNEIGH];
    __shared__ float red[8][3];

    const int tid  = threadIdx.x;
    const int gidx = blockIdx.x;             // b*NATOM + a
    const int b    = gidx / NATOM;

    if (tid < NNEIGH)
        sn[tid] = neighbor[(long)gidx * NNEIGH + tid];
    __syncthreads();

    // Gather dE rows (index 0 -> zero pad row); mostly coalesced, L2-resident
    for (int i = tid; i < NNEIGH * NFEAT; i += 256) {
        const int n = i / NFEAT;
        const int f = i - n * NFEAT;
        const int j = sn[n];
        sg[i] = j ? g_dE[((long)b * NATOM + (j - 1)) * NFEAT + f] : 0.0f;
    }
    __syncthreads();

    const float4* df = (const float4*)(dfeat + (long)gidx * (NNEIGH * NFEAT * 3));
    float ax = 0.0f, ay = 0.0f, az = 0.0f;

    // 1050 groups of 4 (n,f)-pairs; elements 12q..12q+11 decompose as:
    // v0 = {p0k0,p0k1,p0k2,p1k0}, v1 = {p1k1,p1k2,p2k0,p2k1}, v2 = {p2k2,p3k0,p3k1,p3k2}
    for (int q = tid; q < (NNEIGH * NFEAT) / 4; q += 256) {
        const float4 v0 = df[q * 3 + 0];
        const float4 v1 = df[q * 3 + 1];
        const float4 v2 = df[q * 3 + 2];
        const float4 g4 = *(const float4*)(&sg[4 * q]);
        ax += g4.x * v0.x + g4.y * v0.w + g4.z * v1.z + g4.w * v2.y;
        ay += g4.x * v0.y + g4.y * v1.x + g4.z * v1.w + g4.w * v2.z;
        az += g4.x * v0.z + g4.y * v1.y + g4.z * v2.x + g4.w * v2.w;
    }

    #pragma unroll
    for (int o = 16; o > 0; o >>= 1) {
        ax += __shfl_down_sync(0xffffffffu, ax, o);
        ay += __shfl_down_sync(0xffffffffu, ay, o);
        az += __shfl_down_sync(0xffffffffu, az, o);
    }
    const int w = tid >> 5, l = tid & 31;
    if (l == 0) { red[w][0] = ax; red[w][1] = ay; red[w][2] = az; }
    __syncthreads();
    if (tid < 3) {
        float s = 0.0f;
        #pragma unroll
        for (int ww = 0; ww < 8; ww++) s += red[ww][tid];
        out[8 + NB * NATOM + (long)gidx * 3 + tid] = s;
    }
}

// ---------------------------------------------------------------------------
// Launch: out layout = [Etot(8) | Ei(4096) | Force(12288)] = 16392 f32
// ---------------------------------------------------------------------------
extern "C" void kernel_launch(void* const* d_in, const int* in_sizes, int n_in,
                              void* d_out, int out_size)
{
    const float* image    = (const float*)d_in[0];
    const float* dfeat    = (const float*)d_in[1];
    const int*   neighbor = (const int*)d_in[2];
    // d_in[3] = natoms_img (unused)
    const float* W0 = (const float*)d_in[4];
    const float* b0 = (const float*)d_in[5];
    const float* W1 = (const float*)d_in[6];
    const float* b1 = (const float*)d_in[7];
    const float* W2 = (const float*)d_in[8];
    const float* b2 = (const float*)d_in[9];
    float* out = (float*)d_out;

    ei_kernel<<<(NB * NATOM) / 16, 128>>>(image, W0, b0, W1, b1, W2, b2, out);
    etot_kernel<<<NB, 256>>>(out);
    force_kernel<<<NB * NATOM, 256>>>(dfeat, neighbor, out);
}